// round 14
// baseline (speedup 1.0000x reference)
#include <cuda_runtime.h>
#include <math.h>

#define NTOK 2048
#define DDIM 512
#define FDIM 2048
#define NEXP 8
#define BN 128
#define BK 16
#define GS_A 20   // 8-row A-dup group: 16 data floats + 4 pad (80B stride)
#define GS_B 12   // 8-col B group: 8 data floats + 4 pad (48B stride)
#define KSPLIT 4
#define SPLITK (FDIM / KSPLIT)   // 512

__device__ int   g_counts[NEXP];
__device__ int   g_lists[NEXP * NTOK];
__device__ float g_gatew[NTOK * 2];
__device__ float g_h [(size_t)NEXP * NTOK * FDIM];
__device__ float g_hs[(size_t)NTOK * FDIM];

typedef unsigned long long ull;
__device__ __forceinline__ ull fma2(ull a, ull b, ull c) {
    ull d;
    asm("fma.rn.f32x2 %0, %1, %2, %3;" : "=l"(d) : "l"(a), "l"(b), "l"(c));
    return d;
}
__device__ __forceinline__ float2 unpack2(ull v) {
    float2 r;
    asm("mov.b64 {%0, %1}, %2;" : "=f"(r.x), "=f"(r.y) : "l"(v));
    return r;
}
__device__ __forceinline__ void red4(float* p, float a, float b, float c, float d) {
    asm volatile("red.global.add.v4.f32 [%0], {%1, %2, %3, %4};"
                 :: "l"(p), "f"(a), "f"(b), "f"(c), "f"(d) : "memory");
}

// ---------------------------------------------------------------------------
__global__ void zero_counts_kernel() { if (threadIdx.x < NEXP) g_counts[threadIdx.x] = 0; }

__global__ void zero_out_kernel(float* __restrict__ out) {
    int i = blockIdx.x * 256 + threadIdx.x;
    ((float4*)out)[i] = make_float4(0.f, 0.f, 0.f, 0.f);
}

__global__ void gate_kernel(const float* __restrict__ x, const float* __restrict__ Wg,
                            const float* __restrict__ bg) {
    int warp = threadIdx.x >> 5, lane = threadIdx.x & 31;
    int t = blockIdx.x * 4 + warp;
    const float* xr = x + (size_t)t * DDIM;
    float acc[NEXP];
#pragma unroll
    for (int e = 0; e < NEXP; e++) acc[e] = 0.f;
#pragma unroll
    for (int i = 0; i < DDIM / 32; i++) {
        float xv = xr[i * 32 + lane];
#pragma unroll
        for (int e = 0; e < NEXP; e++) acc[e] += xv * Wg[(i * 32 + lane) * NEXP + e];
    }
#pragma unroll
    for (int e = 0; e < NEXP; e++)
#pragma unroll
        for (int off = 16; off > 0; off >>= 1)
            acc[e] += __shfl_down_sync(0xFFFFFFFFu, acc[e], off);
    if (lane == 0) {
        float lg[NEXP];
#pragma unroll
        for (int e = 0; e < NEXP; e++) lg[e] = acc[e] + bg[e];
        int i0 = 0;
#pragma unroll
        for (int e = 1; e < NEXP; e++) if (lg[e] > lg[i0]) i0 = e;
        int i1 = -1;
#pragma unroll
        for (int e = 0; e < NEXP; e++) {
            if (e == i0) continue;
            if (i1 < 0 || lg[e] > lg[i1]) i1 = e;
        }
        float z = expf(lg[i1] - lg[i0]);
        float w0 = 1.f / (1.f + z);
        g_gatew[t * 2 + 0] = w0;
        g_gatew[t * 2 + 1] = z * w0;
        int p0 = atomicAdd(&g_counts[i0], 1);
        g_lists[i0 * NTOK + p0] = t * 2 + 0;
        int p1 = atomicAdd(&g_counts[i1], 1);
        g_lists[i1 * NTOK + p1] = t * 2 + 1;
    }
}

// ---------------------------------------------------------------------------
// FFMA2 GEMM. Lane computes 8M x (NI*2)N. BMT=128: warps 4Mx2N (tile 32x64).
// BMT=64: warps 2Mx4N (tile 32x32). LDS.128 fragment loads, K-major A and B^T-free.
// PHASE 1 (BMT=128): z=0..8: C = relu(A@B + bias) -> g_h / g_hs. K=512.
// PHASE 2 (BMT=64): zi=z%9, split=z/9; K-chunk [split*512,+512); red-accumulate out.
template <int PHASE, int BMT, int NI>
__global__ __launch_bounds__(256, 2)
void mm_kernel(const float* __restrict__ x,
               const float* __restrict__ W1, const float* __restrict__ b1,
               const float* __restrict__ W2, const float* __restrict__ b2,
               const float* __restrict__ Ws1, const float* __restrict__ bs1,
               const float* __restrict__ Ws2, const float* __restrict__ bs2,
               float* __restrict__ out) {
    constexpr int KLOOP = 512;
    constexpr int NN = (PHASE == 1) ? FDIM : DDIM;
    constexpr int AK = (PHASE == 1) ? DDIM : FDIM;
    constexpr int NGROUP = BMT / 8;          // A-dup groups
    constexpr int TPR = 256 / BMT;           // A-loader threads per row
    constexpr int KPT = BK / TPR;            // k-floats per A-loader thread
    const int zi    = (PHASE == 1) ? blockIdx.z : (blockIdx.z % (NEXP + 1));
    const int split = (PHASE == 1) ? 0 : (blockIdx.z / (NEXP + 1));
    const int kbase = split * SPLITK;
    const bool se = (zi == NEXP);
    const int Mrows = se ? NTOK : g_counts[zi];
    const int m0 = blockIdx.y * BMT;
    if (m0 >= Mrows) return;
    const int n0 = blockIdx.x * BN;

    const float* A;
    const float* B;
    const float* bv;
    if (PHASE == 1) {
        A  = x;
        B  = se ? Ws1 : W1 + (size_t)zi * DDIM * FDIM;
        bv = se ? bs1 : b1 + (size_t)zi * FDIM;
    } else {
        A  = se ? g_hs : g_h + (size_t)zi * NTOK * FDIM;
        B  = se ? Ws2 : W2 + (size_t)zi * FDIM * DDIM;
        bv = se ? bs2 : b2 + (size_t)zi * DDIM;
    }

    __shared__ float As2[BK][NGROUP * GS_A];
    __shared__ float Bs [BK][16 * GS_B];
    __shared__ int rowsrc[BMT];

    const int tid = threadIdx.x;
    if (tid < BMT) {
        int gr = m0 + tid, src = -1;
        if (gr < Mrows)
            src = (PHASE == 1 && !se) ? (g_lists[zi * NTOK + gr] >> 1) : gr;
        rowsrc[tid] = src;
    }
    __syncthreads();

    // Loaders
    const int lrow = tid / TPR;
    const int kofs = (tid % TPR) * KPT;
    const int a_st = (lrow >> 3) * GS_A + (lrow & 7) * 2;
    const int asrc = rowsrc[lrow];
    const float* agp = A + (size_t)(asrc < 0 ? 0 : asrc) * AK + kbase;
    const int kr = tid >> 5;
    const int c4 = (tid & 31) * 4;
    const int b_st = (c4 >> 3) * GS_B + (c4 & 7);
    const float* bgp = B + (size_t)kbase * NN + n0 + c4;

    // Fragment geometry
    const int lane = tid & 31;
    const int wid = tid >> 5;
    const int am = lane >> 3;                 // 0..3 (8-row subgroup)
    const int bn = lane & 7;                  // 0..7
    int warpM, ncol;                          // lane's N start within BN
    if (BMT == 128) { warpM = wid & 3;  ncol = (wid >> 2) * 64 + bn * 8; }
    else            { warpM = wid & 1;  ncol = (wid >> 1) * 32 + bn * 4; }
    const int a_off = (warpM * 4 + am) * GS_A;
    const int b_off = (ncol >> 3) * GS_B + (ncol & 7);

    float4 pa0, pa1, pb0, pb1;
    auto loadregs = [&](int kt) {
        if (asrc >= 0) {
            pa0 = *(const float4*)(agp + kt + kofs);
            if (KPT == 8) pa1 = *(const float4*)(agp + kt + kofs + 4);
        } else {
            pa0 = make_float4(0.f, 0.f, 0.f, 0.f);
            pa1 = pa0;
        }
        pb0 = *(const float4*)(bgp + (size_t)(kt + kr) * NN);
        pb1 = *(const float4*)(bgp + (size_t)(kt + kr + 8) * NN);
    };
    auto storesm = [&]() {
        *(float2*)&As2[kofs + 0][a_st] = make_float2(pa0.x, pa0.x);
        *(float2*)&As2[kofs + 1][a_st] = make_float2(pa0.y, pa0.y);
        *(float2*)&As2[kofs + 2][a_st] = make_float2(pa0.z, pa0.z);
        *(float2*)&As2[kofs + 3][a_st] = make_float2(pa0.w, pa0.w);
        if (KPT == 8) {
            *(float2*)&As2[kofs + 4][a_st] = make_float2(pa1.x, pa1.x);
            *(float2*)&As2[kofs + 5][a_st] = make_float2(pa1.y, pa1.y);
            *(float2*)&As2[kofs + 6][a_st] = make_float2(pa1.z, pa1.z);
            *(float2*)&As2[kofs + 7][a_st] = make_float2(pa1.w, pa1.w);
        }
        *(float4*)&Bs[kr][b_st]     = pb0;
        *(float4*)&Bs[kr + 8][b_st] = pb1;
    };

    ull acc[8][NI];
#pragma unroll
    for (int i = 0; i < 8; i++)
#pragma unroll
        for (int j = 0; j < NI; j++) acc[i][j] = 0ull;

    loadregs(0);
    storesm();

    for (int kt = 0; kt < KLOOP; kt += BK) {
        __syncthreads();
        if (kt + BK < KLOOP) loadregs(kt + BK);

#pragma unroll
        for (int k = 0; k < BK; k++) {
            const ulonglong2* ap = (const ulonglong2*)&As2[k][a_off];
            ulonglong2 qa0 = ap[0], qa1 = ap[1], qa2 = ap[2], qa3 = ap[3];
            ull a[8] = {qa0.x, qa0.y, qa1.x, qa1.y, qa2.x, qa2.y, qa3.x, qa3.y};
            ull b[NI];
            const ulonglong2* bp = (const ulonglong2*)&Bs[k][b_off];
            ulonglong2 qb0 = bp[0];
            b[0] = qb0.x; b[1] = qb0.y;
            if (NI == 4) {
                ulonglong2 qb1 = bp[1];
                b[2] = qb1.x; b[3] = qb1.y;
            }
#pragma unroll
            for (int i = 0; i < 8; i++) {
#pragma unroll
                for (int j = 0; j < NI; j++) acc[i][j] = fma2(a[i], b[j], acc[i][j]);
            }
        }
        if (kt + BK < KLOOP) {
            __syncthreads();
            storesm();
        }
    }

    // ---------------- epilogue ----------------
    const int cn = n0 + ncol;
    const float bscale = (PHASE == 1 || split == 0) ? 1.f : 0.f;
    float bb[NI * 2];
#pragma unroll
    for (int j = 0; j < NI * 2; j++) bb[j] = bv[cn + j] * bscale;
    const int mrow0 = m0 + warpM * 32 + am * 8;

#pragma unroll
    for (int i = 0; i < 8; i++) {
        const int m = mrow0 + i;
        if (m >= Mrows) continue;
        float v[NI * 2];
#pragma unroll
        for (int j = 0; j < NI; j++) {
            float2 p = unpack2(acc[i][j]);
            v[2 * j]     = p.x + bb[2 * j];
            v[2 * j + 1] = p.y + bb[2 * j + 1];
        }
        if (PHASE == 1) {
            float* C = (se ? g_hs : g_h + (size_t)zi * NTOK * FDIM) + (size_t)m * FDIM + cn;
#pragma unroll
            for (int j = 0; j < NI * 2; j += 4)
                *(float4*)(C + j) = make_float4(fmaxf(v[j], 0.f), fmaxf(v[j + 1], 0.f),
                                                fmaxf(v[j + 2], 0.f), fmaxf(v[j + 3], 0.f));
        } else {
            float w;
            int row;
            if (se) { w = 0.5f; row = m; }
            else {
                int entry = g_lists[zi * NTOK + m];
                w = g_gatew[entry];
                row = entry >> 1;
            }
            float* C = out + (size_t)row * DDIM + cn;
#pragma unroll
            for (int j = 0; j < NI * 2; j += 4)
                red4(C + j, w * v[j], w * v[j + 1], w * v[j + 2], w * v[j + 3]);
        }
    }
}

// ---------------------------------------------------------------------------
extern "C" void kernel_launch(void* const* d_in, const int* in_sizes, int n_in,
                              void* d_out, int out_size) {
    const float* x   = (const float*)d_in[0];
    const float* Wg  = (const float*)d_in[1];
    const float* bg  = (const float*)d_in[2];
    const float* W1  = (const float*)d_in[3];
    const float* b1  = (const float*)d_in[4];
    const float* W2  = (const float*)d_in[5];
    const float* b2  = (const float*)d_in[6];
    const float* Ws1 = (const float*)d_in[7];
    const float* bs1 = (const float*)d_in[8];
    const float* Ws2 = (const float*)d_in[9];
    const float* bs2 = (const float*)d_in[10];
    float* out = (float*)d_out;

    zero_counts_kernel<<<1, 32>>>();
    zero_out_kernel<<<(NTOK * DDIM / 4) / 256, 256>>>(out);
    gate_kernel<<<NTOK / 4, 128>>>(x, Wg, bg);

    // Phase 1: all FFN1 (8 routed + shared). K=512, N=2048, BM=128.
    mm_kernel<1, 128, 4><<<dim3(FDIM / BN, NTOK / 128, NEXP + 1), 256>>>(
        x, W1, b1, W2, b2, Ws1, bs1, Ws2, bs2, out);
    // Phase 2: all FFN2, K split 4 ways, BM=64, vector-red accumulate. N=512.
    mm_kernel<2, 64, 2><<<dim3(DDIM / BN, NTOK / 64, (NEXP + 1) * KSPLIT), 256>>>(
        x, W1, b1, W2, b2, Ws1, bs1, Ws2, bs2, out);
}

// round 15
// speedup vs baseline: 1.1996x; 1.1996x over previous
#include <cuda_runtime.h>
#include <math.h>

#define NTOK 2048
#define DDIM 512
#define FDIM 2048
#define NEXP 8
#define BM 128
#define BN 128
#define BK 16
#define GS_A 20   // 8-row A-dup group: 16 data floats + 4 pad (80B stride)
#define GS_B 12   // 8-col B group: 8 data floats + 4 pad (48B stride)
#define KSPLIT 4
#define SPLITK (FDIM / KSPLIT)   // 512

__device__ int   g_counts[NEXP];
__device__ int   g_lists[NEXP * NTOK];
__device__ float g_gatew[NTOK * 2];
__device__ float g_h [(size_t)NEXP * NTOK * FDIM];
__device__ float g_hs[(size_t)NTOK * FDIM];

typedef unsigned long long ull;
__device__ __forceinline__ ull fma2(ull a, ull b, ull c) {
    ull d;
    asm("fma.rn.f32x2 %0, %1, %2, %3;" : "=l"(d) : "l"(a), "l"(b), "l"(c));
    return d;
}
__device__ __forceinline__ float2 unpack2(ull v) {
    float2 r;
    asm("mov.b64 {%0, %1}, %2;" : "=f"(r.x), "=f"(r.y) : "l"(v));
    return r;
}
__device__ __forceinline__ void red4(float* p, float a, float b, float c, float d) {
    asm volatile("red.global.add.v4.f32 [%0], {%1, %2, %3, %4};"
                 :: "l"(p), "f"(a), "f"(b), "f"(c), "f"(d) : "memory");
}

// ---------------------------------------------------------------------------
__global__ void zero_counts_kernel() { if (threadIdx.x < NEXP) g_counts[threadIdx.x] = 0; }

__global__ void zero_out_kernel(float* __restrict__ out) {
    int i = blockIdx.x * 256 + threadIdx.x;
    ((float4*)out)[i] = make_float4(0.f, 0.f, 0.f, 0.f);
}

__global__ void gate_kernel(const float* __restrict__ x, const float* __restrict__ Wg,
                            const float* __restrict__ bg) {
    int warp = threadIdx.x >> 5, lane = threadIdx.x & 31;
    int t = blockIdx.x * 4 + warp;
    const float* xr = x + (size_t)t * DDIM;
    float acc[NEXP];
#pragma unroll
    for (int e = 0; e < NEXP; e++) acc[e] = 0.f;
#pragma unroll
    for (int i = 0; i < DDIM / 32; i++) {
        float xv = xr[i * 32 + lane];
#pragma unroll
        for (int e = 0; e < NEXP; e++) acc[e] += xv * Wg[(i * 32 + lane) * NEXP + e];
    }
#pragma unroll
    for (int e = 0; e < NEXP; e++)
#pragma unroll
        for (int off = 16; off > 0; off >>= 1)
            acc[e] += __shfl_down_sync(0xFFFFFFFFu, acc[e], off);
    if (lane == 0) {
        float lg[NEXP];
#pragma unroll
        for (int e = 0; e < NEXP; e++) lg[e] = acc[e] + bg[e];
        int i0 = 0;
#pragma unroll
        for (int e = 1; e < NEXP; e++) if (lg[e] > lg[i0]) i0 = e;
        int i1 = -1;
#pragma unroll
        for (int e = 0; e < NEXP; e++) {
            if (e == i0) continue;
            if (i1 < 0 || lg[e] > lg[i1]) i1 = e;
        }
        float z = expf(lg[i1] - lg[i0]);
        float w0 = 1.f / (1.f + z);
        g_gatew[t * 2 + 0] = w0;
        g_gatew[t * 2 + 1] = z * w0;
        int p0 = atomicAdd(&g_counts[i0], 1);
        g_lists[i0 * NTOK + p0] = t * 2 + 0;
        int p1 = atomicAdd(&g_counts[i1], 1);
        g_lists[i1 * NTOK + p1] = t * 2 + 1;
    }
}

// ---------------------------------------------------------------------------
// FFMA2 GEMM (R12 geometry: warp tile 32Mx64N, lane tile 8Mx8N, BK=16).
// PHASE 1: z = 0..8 (8 routed + shared): C = relu(A@B + bias) -> g_h / g_hs. K=512.
// PHASE 2: zi = z%9, split = z/9; K-chunk [split*512, +512) of K=2048;
//          red.global(out[row], w*(A@B)), bias folded into split 0.
template <int PHASE>
__global__ __launch_bounds__(256, 2)
void mm_kernel(const float* __restrict__ x,
               const float* __restrict__ W1, const float* __restrict__ b1,
               const float* __restrict__ W2, const float* __restrict__ b2,
               const float* __restrict__ Ws1, const float* __restrict__ bs1,
               const float* __restrict__ Ws2, const float* __restrict__ bs2,
               float* __restrict__ out) {
    constexpr int KLOOP = 512;
    constexpr int NN = (PHASE == 1) ? FDIM : DDIM;
    constexpr int AK = (PHASE == 1) ? DDIM : FDIM;
    const int zi    = (PHASE == 1) ? blockIdx.z : (blockIdx.z % (NEXP + 1));
    const int split = (PHASE == 1) ? 0 : (blockIdx.z / (NEXP + 1));
    const int kbase = split * SPLITK;
    const bool se = (zi == NEXP);
    const int Mrows = se ? NTOK : g_counts[zi];
    const int m0 = blockIdx.y * BM;
    if (m0 >= Mrows) return;
    const int n0 = blockIdx.x * BN;

    const float* A;
    const float* B;
    const float* bv;
    if (PHASE == 1) {
        A  = x;
        B  = se ? Ws1 : W1 + (size_t)zi * DDIM * FDIM;
        bv = se ? bs1 : b1 + (size_t)zi * FDIM;
    } else {
        A  = se ? g_hs : g_h + (size_t)zi * NTOK * FDIM;
        B  = se ? Ws2 : W2 + (size_t)zi * FDIM * DDIM;
        bv = se ? bs2 : b2 + (size_t)zi * DDIM;
    }

    __shared__ float As2[BK][16 * GS_A];
    __shared__ float Bs [BK][16 * GS_B];
    __shared__ int rowsrc[BM];

    const int tid = threadIdx.x;
    const int lrow = tid >> 1;
    const int kofs = (tid & 1) * 8;

    // Row gather indices: smem path only for phase-1 routed; direct otherwise.
    int asrc;
    if (PHASE == 1 && !se) {
        if (tid < BM) {
            int gr = m0 + tid;
            rowsrc[tid] = (gr < Mrows) ? (g_lists[zi * NTOK + gr] >> 1) : -1;
        }
        __syncthreads();
        asrc = rowsrc[lrow];
    } else {
        int gr = m0 + lrow;
        asrc = (gr < Mrows) ? gr : -1;
    }

    const int a_st = (lrow >> 3) * GS_A + (lrow & 7) * 2;
    const float* agp = A + (size_t)(asrc < 0 ? 0 : asrc) * AK + kbase;
    const int kr = tid >> 5;
    const int c4 = (tid & 31) * 4;
    const int b_st = (c4 >> 3) * GS_B + (c4 & 7);
    const float* bgp = B + (size_t)kbase * NN + n0 + c4;

    // Fragment geometry
    const int lane = tid & 31;
    const int wid = tid >> 5;
    const int warpM = wid & 3;
    const int warpN = wid >> 2;
    const int am = lane >> 3;
    const int bn = lane & 7;
    const int a_off = (warpM * 4 + am) * GS_A;
    const int b_off = (warpN * 8 + bn) * GS_B;

    float4 pa0, pa1, pb0, pb1;
    auto loadregs = [&](int kt) {
        if (asrc >= 0) {
            pa0 = __ldg((const float4*)(agp + kt + kofs));
            pa1 = __ldg((const float4*)(agp + kt + kofs + 4));
        } else {
            pa0 = make_float4(0.f, 0.f, 0.f, 0.f);
            pa1 = pa0;
        }
        pb0 = __ldg((const float4*)(bgp + (size_t)(kt + kr) * NN));
        pb1 = __ldg((const float4*)(bgp + (size_t)(kt + kr + 8) * NN));
    };
    auto storesm = [&]() {
        *(float2*)&As2[kofs + 0][a_st] = make_float2(pa0.x, pa0.x);
        *(float2*)&As2[kofs + 1][a_st] = make_float2(pa0.y, pa0.y);
        *(float2*)&As2[kofs + 2][a_st] = make_float2(pa0.z, pa0.z);
        *(float2*)&As2[kofs + 3][a_st] = make_float2(pa0.w, pa0.w);
        *(float2*)&As2[kofs + 4][a_st] = make_float2(pa1.x, pa1.x);
        *(float2*)&As2[kofs + 5][a_st] = make_float2(pa1.y, pa1.y);
        *(float2*)&As2[kofs + 6][a_st] = make_float2(pa1.z, pa1.z);
        *(float2*)&As2[kofs + 7][a_st] = make_float2(pa1.w, pa1.w);
        *(float4*)&Bs[kr][b_st]     = pb0;
        *(float4*)&Bs[kr + 8][b_st] = pb1;
    };

    ull acc[8][4];
#pragma unroll
    for (int i = 0; i < 8; i++)
#pragma unroll
        for (int j = 0; j < 4; j++) acc[i][j] = 0ull;

    loadregs(0);
    storesm();

#pragma unroll 1
    for (int kt = 0; kt < KLOOP; kt += BK) {
        __syncthreads();
        if (kt + BK < KLOOP) loadregs(kt + BK);

#pragma unroll
        for (int k = 0; k < BK; k++) {
            const ulonglong2* ap = (const ulonglong2*)&As2[k][a_off];
            ulonglong2 qa0 = ap[0], qa1 = ap[1], qa2 = ap[2], qa3 = ap[3];
            const ulonglong2* bp = (const ulonglong2*)&Bs[k][b_off];
            ulonglong2 qb0 = bp[0], qb1 = bp[1];
            ull a[8] = {qa0.x, qa0.y, qa1.x, qa1.y, qa2.x, qa2.y, qa3.x, qa3.y};
            ull b[4] = {qb0.x, qb0.y, qb1.x, qb1.y};
#pragma unroll
            for (int i = 0; i < 8; i++) {
                acc[i][0] = fma2(a[i], b[0], acc[i][0]);
                acc[i][1] = fma2(a[i], b[1], acc[i][1]);
                acc[i][2] = fma2(a[i], b[2], acc[i][2]);
                acc[i][3] = fma2(a[i], b[3], acc[i][3]);
            }
        }
        if (kt + BK < KLOOP) {
            __syncthreads();
            storesm();
        }
    }

    // ---------------- epilogue ----------------
    const int cn = n0 + warpN * 64 + bn * 8;
    const float bscale = (PHASE == 1 || split == 0) ? 1.f : 0.f;
    float4 bb0 = *(const float4*)(bv + cn);
    float4 bb1 = *(const float4*)(bv + cn + 4);
    bb0.x *= bscale; bb0.y *= bscale; bb0.z *= bscale; bb0.w *= bscale;
    bb1.x *= bscale; bb1.y *= bscale; bb1.z *= bscale; bb1.w *= bscale;
    const int mrow0 = m0 + warpM * 32 + am * 8;

#pragma unroll
    for (int i = 0; i < 8; i++) {
        const int m = mrow0 + i;
        if (m >= Mrows) continue;
        float2 v0 = unpack2(acc[i][0]);
        float2 v1 = unpack2(acc[i][1]);
        float2 v2 = unpack2(acc[i][2]);
        float2 v3 = unpack2(acc[i][3]);
        v0.x += bb0.x; v0.y += bb0.y;
        v1.x += bb0.z; v1.y += bb0.w;
        v2.x += bb1.x; v2.y += bb1.y;
        v3.x += bb1.z; v3.y += bb1.w;
        if (PHASE == 1) {
            float* C = (se ? g_hs : g_h + (size_t)zi * NTOK * FDIM) + (size_t)m * FDIM + cn;
            *(float4*)(C)     = make_float4(fmaxf(v0.x, 0.f), fmaxf(v0.y, 0.f),
                                            fmaxf(v1.x, 0.f), fmaxf(v1.y, 0.f));
            *(float4*)(C + 4) = make_float4(fmaxf(v2.x, 0.f), fmaxf(v2.y, 0.f),
                                            fmaxf(v3.x, 0.f), fmaxf(v3.y, 0.f));
        } else {
            float w;
            int row;
            if (se) { w = 0.5f; row = m; }
            else {
                int entry = g_lists[zi * NTOK + m];
                w = g_gatew[entry];
                row = entry >> 1;
            }
            float* C = out + (size_t)row * DDIM + cn;
            red4(C,     w * v0.x, w * v0.y, w * v1.x, w * v1.y);
            red4(C + 4, w * v2.x, w * v2.y, w * v3.x, w * v3.y);
        }
    }
}

// ---------------------------------------------------------------------------
extern "C" void kernel_launch(void* const* d_in, const int* in_sizes, int n_in,
                              void* d_out, int out_size) {
    const float* x   = (const float*)d_in[0];
    const float* Wg  = (const float*)d_in[1];
    const float* bg  = (const float*)d_in[2];
    const float* W1  = (const float*)d_in[3];
    const float* b1  = (const float*)d_in[4];
    const float* W2  = (const float*)d_in[5];
    const float* b2  = (const float*)d_in[6];
    const float* Ws1 = (const float*)d_in[7];
    const float* bs1 = (const float*)d_in[8];
    const float* Ws2 = (const float*)d_in[9];
    const float* bs2 = (const float*)d_in[10];
    float* out = (float*)d_out;

    zero_counts_kernel<<<1, 32>>>();
    zero_out_kernel<<<(NTOK * DDIM / 4) / 256, 256>>>(out);
    gate_kernel<<<NTOK / 4, 128>>>(x, Wg, bg);

    // Phase 1: all FFN1 (8 routed + shared). K=512, N=2048, BM=128.
    mm_kernel<1><<<dim3(FDIM / BN, NTOK / BM, NEXP + 1), 256>>>(
        x, W1, b1, W2, b2, Ws1, bs1, Ws2, bs2, out);
    // Phase 2: all FFN2, K=2048 split 4 ways, BM=128, vector-red accumulate. N=512.
    mm_kernel<2><<<dim3(DDIM / BN, NTOK / BM, (NEXP + 1) * KSPLIT), 256>>>(
        x, W1, b1, W2, b2, Ws1, bs1, Ws2, bs2, out);
}

// round 17
// speedup vs baseline: 1.2748x; 1.0627x over previous
#include <cuda_runtime.h>
#include <math.h>

#define NTOK 2048
#define DDIM 512
#define FDIM 2048
#define NEXP 8
#define BM 64
#define BN 128
#define BK 16
#define NTHR 128
#define GS_A 20   // 8-row A-dup group: 16 data floats + 4 pad (80B stride)
#define GS_B 12   // 8-col B group: 8 data floats + 4 pad (48B stride)
#define KSPLIT 4
#define SPLITK (FDIM / KSPLIT)   // 512

__device__ int   g_counts[NEXP];
__device__ int   g_lists[NEXP * NTOK];
__device__ float g_gatew[NTOK * 2];
__device__ float g_h [(size_t)NEXP * NTOK * FDIM];
__device__ float g_hs[(size_t)NTOK * FDIM];

typedef unsigned long long ull;
__device__ __forceinline__ ull fma2(ull a, ull b, ull c) {
    ull d;
    asm("fma.rn.f32x2 %0, %1, %2, %3;" : "=l"(d) : "l"(a), "l"(b), "l"(c));
    return d;
}
__device__ __forceinline__ float2 unpack2(ull v) {
    float2 r;
    asm("mov.b64 {%0, %1}, %2;" : "=f"(r.x), "=f"(r.y) : "l"(v));
    return r;
}
__device__ __forceinline__ void red4(float* p, float a, float b, float c, float d) {
    asm volatile("red.global.add.v4.f32 [%0], {%1, %2, %3, %4};"
                 :: "l"(p), "f"(a), "f"(b), "f"(c), "f"(d) : "memory");
}

// ---------------------------------------------------------------------------
__global__ void zero_counts_kernel() { if (threadIdx.x < NEXP) g_counts[threadIdx.x] = 0; }

// Gate + zero-out fused: block b handles tokens 4b..4b+3 (one per warp) and
// zeroes their out rows.
__global__ void gate_kernel(const float* __restrict__ x, const float* __restrict__ Wg,
                            const float* __restrict__ bg, float* __restrict__ out) {
    int warp = threadIdx.x >> 5, lane = threadIdx.x & 31;
    int t = blockIdx.x * 4 + warp;

    // zero out rows for this block's 4 tokens (512 floats each)
    {
        float4* op = (float4*)(out + (size_t)blockIdx.x * 4 * DDIM);
#pragma unroll
        for (int i = 0; i < 4; i++)
            op[i * 128 + threadIdx.x] = make_float4(0.f, 0.f, 0.f, 0.f);
    }

    const float* xr = x + (size_t)t * DDIM;
    float acc[NEXP];
#pragma unroll
    for (int e = 0; e < NEXP; e++) acc[e] = 0.f;
#pragma unroll
    for (int i = 0; i < DDIM / 32; i++) {
        float xv = xr[i * 32 + lane];
#pragma unroll
        for (int e = 0; e < NEXP; e++) acc[e] += xv * Wg[(i * 32 + lane) * NEXP + e];
    }
#pragma unroll
    for (int e = 0; e < NEXP; e++)
#pragma unroll
        for (int off = 16; off > 0; off >>= 1)
            acc[e] += __shfl_down_sync(0xFFFFFFFFu, acc[e], off);
    if (lane == 0) {
        float lg[NEXP];
#pragma unroll
        for (int e = 0; e < NEXP; e++) lg[e] = acc[e] + bg[e];
        int i0 = 0;
#pragma unroll
        for (int e = 1; e < NEXP; e++) if (lg[e] > lg[i0]) i0 = e;
        int i1 = -1;
#pragma unroll
        for (int e = 0; e < NEXP; e++) {
            if (e == i0) continue;
            if (i1 < 0 || lg[e] > lg[i1]) i1 = e;
        }
        float z = expf(lg[i1] - lg[i0]);
        float w0 = 1.f / (1.f + z);
        g_gatew[t * 2 + 0] = w0;
        g_gatew[t * 2 + 1] = z * w0;
        int p0 = atomicAdd(&g_counts[i0], 1);
        g_lists[i0 * NTOK + p0] = t * 2 + 0;
        int p1 = atomicAdd(&g_counts[i1], 1);
        g_lists[i1 * NTOK + p1] = t * 2 + 1;
    }
}

// ---------------------------------------------------------------------------
// FFMA2 GEMM. CTA 64Mx128N, 128 threads, 4 warps (2Mx2N), warp tile 32x64,
// lane tile 8Mx8N (same instruction mix as the BM=128 version), BK=16.
// PHASE 1: z = 0..8 (8 routed + shared): C = relu(A@B + bias) -> g_h / g_hs. K=512.
// PHASE 2: zi = z%9, split = z/9; K-chunk [split*512, +512) of K=2048;
//          red.global(out[row], w*(A@B)), bias folded into split 0.
template <int PHASE>
__global__ __launch_bounds__(NTHR, 4)
void mm_kernel(const float* __restrict__ x,
               const float* __restrict__ W1, const float* __restrict__ b1,
               const float* __restrict__ W2, const float* __restrict__ b2,
               const float* __restrict__ Ws1, const float* __restrict__ bs1,
               const float* __restrict__ Ws2, const float* __restrict__ bs2,
               float* __restrict__ out) {
    constexpr int KLOOP = 512;
    constexpr int NN = (PHASE == 1) ? FDIM : DDIM;
    constexpr int AK = (PHASE == 1) ? DDIM : FDIM;
    const int zi    = (PHASE == 1) ? blockIdx.z : (blockIdx.z % (NEXP + 1));
    const int split = (PHASE == 1) ? 0 : (blockIdx.z / (NEXP + 1));
    const int kbase = split * SPLITK;
    const bool se = (zi == NEXP);
    const int Mrows = se ? NTOK : g_counts[zi];
    const int m0 = blockIdx.y * BM;
    if (m0 >= Mrows) return;
    const int n0 = blockIdx.x * BN;

    const float* A;
    const float* B;
    const float* bv;
    if (PHASE == 1) {
        A  = x;
        B  = se ? Ws1 : W1 + (size_t)zi * DDIM * FDIM;
        bv = se ? bs1 : b1 + (size_t)zi * FDIM;
    } else {
        A  = se ? g_hs : g_h + (size_t)zi * NTOK * FDIM;
        B  = se ? Ws2 : W2 + (size_t)zi * FDIM * DDIM;
        bv = se ? bs2 : b2 + (size_t)zi * DDIM;
    }

    __shared__ float As2[BK][8 * GS_A];     // 8 dup-groups of 8 rows
    __shared__ float Bs [BK][16 * GS_B];    // 16 groups of 8 cols
    __shared__ int rowsrc[BM];

    const int tid = threadIdx.x;
    const int lrow = tid >> 1;              // 0..63
    const int kofs = (tid & 1) * 8;

    int asrc;
    if (PHASE == 1 && !se) {
        if (tid < BM) {
            int gr = m0 + tid;
            rowsrc[tid] = (gr < Mrows) ? (g_lists[zi * NTOK + gr] >> 1) : -1;
        }
        __syncthreads();
        asrc = rowsrc[lrow];
    } else {
        int gr = m0 + lrow;
        asrc = (gr < Mrows) ? gr : -1;
    }

    const int a_st = (lrow >> 3) * GS_A + (lrow & 7) * 2;
    const float* agp = A + (size_t)(asrc < 0 ? 0 : asrc) * AK + kbase;
    const int kr = tid >> 5;                // 0..3: rows kr, kr+4, kr+8, kr+12
    const int c4 = (tid & 31) * 4;
    const int b_st = (c4 >> 3) * GS_B + (c4 & 7);
    const float* bgp = B + (size_t)kbase * NN + n0 + c4;

    // Fragment geometry (4 warps: 2M x 2N)
    const int lane = tid & 31;
    const int wid = tid >> 5;
    const int warpM = wid & 1;
    const int warpN = wid >> 1;
    const int am = lane >> 3;
    const int bn = lane & 7;
    const int a_off = (warpM * 4 + am) * GS_A;
    const int b_off = (warpN * 8 + bn) * GS_B;

    float4 pa0, pa1, pb[4];
    auto loadregs = [&](int kt) {
        if (asrc >= 0) {
            pa0 = __ldg((const float4*)(agp + kt + kofs));
            pa1 = __ldg((const float4*)(agp + kt + kofs + 4));
        } else {
            pa0 = make_float4(0.f, 0.f, 0.f, 0.f);
            pa1 = pa0;
        }
#pragma unroll
        for (int i = 0; i < 4; i++)
            pb[i] = __ldg((const float4*)(bgp + (size_t)(kt + kr + 4 * i) * NN));
    };
    auto storesm = [&]() {
        *(float2*)&As2[kofs + 0][a_st] = make_float2(pa0.x, pa0.x);
        *(float2*)&As2[kofs + 1][a_st] = make_float2(pa0.y, pa0.y);
        *(float2*)&As2[kofs + 2][a_st] = make_float2(pa0.z, pa0.z);
        *(float2*)&As2[kofs + 3][a_st] = make_float2(pa0.w, pa0.w);
        *(float2*)&As2[kofs + 4][a_st] = make_float2(pa1.x, pa1.x);
        *(float2*)&As2[kofs + 5][a_st] = make_float2(pa1.y, pa1.y);
        *(float2*)&As2[kofs + 6][a_st] = make_float2(pa1.z, pa1.z);
        *(float2*)&As2[kofs + 7][a_st] = make_float2(pa1.w, pa1.w);
#pragma unroll
        for (int i = 0; i < 4; i++)
            *(float4*)&Bs[kr + 4 * i][b_st] = pb[i];
    };

    ull acc[8][4];
#pragma unroll
    for (int i = 0; i < 8; i++)
#pragma unroll
        for (int j = 0; j < 4; j++) acc[i][j] = 0ull;

    loadregs(0);
    storesm();

#pragma unroll 1
    for (int kt = 0; kt < KLOOP; kt += BK) {
        __syncthreads();
        if (kt + BK < KLOOP) loadregs(kt + BK);

#pragma unroll
        for (int k = 0; k < BK; k++) {
            const ulonglong2* ap = (const ulonglong2*)&As2[k][a_off];
            ulonglong2 qa0 = ap[0], qa1 = ap[1], qa2 = ap[2], qa3 = ap[3];
            const ulonglong2* bp = (const ulonglong2*)&Bs[k][b_off];
            ulonglong2 qb0 = bp[0], qb1 = bp[1];
            ull a[8] = {qa0.x, qa0.y, qa1.x, qa1.y, qa2.x, qa2.y, qa3.x, qa3.y};
            ull b[4] = {qb0.x, qb0.y, qb1.x, qb1.y};
#pragma unroll
            for (int i = 0; i < 8; i++) {
                acc[i][0] = fma2(a[i], b[0], acc[i][0]);
                acc[i][1] = fma2(a[i], b[1], acc[i][1]);
                acc[i][2] = fma2(a[i], b[2], acc[i][2]);
                acc[i][3] = fma2(a[i], b[3], acc[i][3]);
            }
        }
        if (kt + BK < KLOOP) {
            __syncthreads();
            storesm();
        }
    }

    // ---------------- epilogue ----------------
    const int cn = n0 + warpN * 64 + bn * 8;
    const float bscale = (PHASE == 1 || split == 0) ? 1.f : 0.f;
    float4 bb0 = *(const float4*)(bv + cn);
    float4 bb1 = *(const float4*)(bv + cn + 4);
    bb0.x *= bscale; bb0.y *= bscale; bb0.z *= bscale; bb0.w *= bscale;
    bb1.x *= bscale; bb1.y *= bscale; bb1.z *= bscale; bb1.w *= bscale;
    const int mrow0 = m0 + warpM * 32 + am * 8;

#pragma unroll
    for (int i = 0; i < 8; i++) {
        const int m = mrow0 + i;
        if (m >= Mrows) continue;
        float2 v0 = unpack2(acc[i][0]);
        float2 v1 = unpack2(acc[i][1]);
        float2 v2 = unpack2(acc[i][2]);
        float2 v3 = unpack2(acc[i][3]);
        v0.x += bb0.x; v0.y += bb0.y;
        v1.x += bb0.z; v1.y += bb0.w;
        v2.x += bb1.x; v2.y += bb1.y;
        v3.x += bb1.z; v3.y += bb1.w;
        if (PHASE == 1) {
            float* C = (se ? g_hs : g_h + (size_t)zi * NTOK * FDIM) + (size_t)m * FDIM + cn;
            *(float4*)(C)     = make_float4(fmaxf(v0.x, 0.f), fmaxf(v0.y, 0.f),
                                            fmaxf(v1.x, 0.f), fmaxf(v1.y, 0.f));
            *(float4*)(C + 4) = make_float4(fmaxf(v2.x, 0.f), fmaxf(v2.y, 0.f),
                                            fmaxf(v3.x, 0.f), fmaxf(v3.y, 0.f));
        } else {
            float w;
            int row;
            if (se) { w = 0.5f; row = m; }
            else {
                int entry = g_lists[zi * NTOK + m];
                w = g_gatew[entry];
                row = entry >> 1;
            }
            float* C = out + (size_t)row * DDIM + cn;
            red4(C,     w * v0.x, w * v0.y, w * v1.x, w * v1.y);
            red4(C + 4, w * v2.x, w * v2.y, w * v3.x, w * v3.y);
        }
    }
}

// ---------------------------------------------------------------------------
extern "C" void kernel_launch(void* const* d_in, const int* in_sizes, int n_in,
                              void* d_out, int out_size) {
    const float* x   = (const float*)d_in[0];
    const float* Wg  = (const float*)d_in[1];
    const float* bg  = (const float*)d_in[2];
    const float* W1  = (const float*)d_in[3];
    const float* b1  = (const float*)d_in[4];
    const float* W2  = (const float*)d_in[5];
    const float* b2  = (const float*)d_in[6];
    const float* Ws1 = (const float*)d_in[7];
    const float* bs1 = (const float*)d_in[8];
    const float* Ws2 = (const float*)d_in[9];
    const float* bs2 = (const float*)d_in[10];
    float* out = (float*)d_out;

    zero_counts_kernel<<<1, 32>>>();
    gate_kernel<<<NTOK / 4, 128>>>(x, Wg, bg, out);

    // Phase 1: all FFN1 (8 routed + shared). K=512, N=2048, BM=64.
    mm_kernel<1><<<dim3(FDIM / BN, NTOK / BM, NEXP + 1), NTHR>>>(
        x, W1, b1, W2, b2, Ws1, bs1, Ws2, bs2, out);
    // Phase 2: all FFN2, K=2048 split 4 ways, BM=64, vector-red accumulate. N=512.
    mm_kernel<2><<<dim3(DDIM / BN, NTOK / BM, (NEXP + 1) * KSPLIT), NTHR>>>(
        x, W1, b1, W2, b2, Ws1, bs1, Ws2, bs2, out);
}